// round 10
// baseline (speedup 1.0000x reference)
#include <cuda_runtime.h>
#include <cstdint>

// Problem constants (fixed by setup_inputs): B=1, H=32, Lq=512, Lk=4096, group_size=4
#define H       32
#define LQ      512
#define LK      4096
#define WORDS   128            // LK / 32
#define NROWS   (H * LQ)       // 16384 blocks, one per row
#define KSEL    819            // int(0.2 * 4096)
#define THRESH  1638           // min(2*819, int(0.75*4096))
#define GS      4
#define NG      8              // H / GS
#define NOT_CHOSEN (1 << 30)
#define MAXCAND 64

// Key-domain window for the 819th-largest of 4096 i.i.d. N(0,1) samples.
// Pivot value concentrates at 0.8416 +- 0.022; window [0.70, 1.00] is ~7 sigma.
// fkey is linear in value on [0.5, 1.0) (one exponent region), so key-binning
// is exact value-binning. Exact fallback handles anything outside the window.
#define KHI 0xBF800000u        // fkey(1.0f)
#define KLO 0xBF333333u        // fkey(0.7f)
#define BSHIFT 14              // bin width = 2^14 keys = 2^-10 in value
#define HSIZE 320              // padded: 10 bins/lane * 32 lanes
#define BPL 10

// Scratch (device globals; zero-initialized at module load; no allocation).
// g_ctr/g_bar1/g_bar2 are MONOTONIC: every execution adds exactly NROWS/H/H,
// so "launch-start value mod N == 0" is an invariant and no reset is needed
// (graph capture records without executing, replays execute fully).
__device__ unsigned g_masks[(size_t)H * LQ * WORDS];   // 8 MB of top-k bitsets
__device__ unsigned g_hunion[H * WORDS];
__device__ int      g_nsel[H];
__device__ unsigned g_ctr;        // row-completion ticket counter
__device__ unsigned g_bar1, g_bar2;

// Order-preserving float -> uint32 map (larger float => larger key)
__device__ __forceinline__ unsigned fkey(float f) {
    unsigned u = __float_as_uint(f);
    return (u & 0x80000000u) ? ~u : (u | 0x80000000u);
}

// ---------------------------------------------------------------------------
// Single fused kernel. Per-block: one row's exact top-k mask (windowed
// key-domain histogram + refinement, exact fallback) + zero the output row.
// The last 32 blocks to finish (ticket counter) become per-head tail workers:
// back-to-front union scan -> nsel, global n_stop, final unions, group-OR,
// last-row write, density. grid = NROWS, 256 threads.
// ---------------------------------------------------------------------------
__global__ void __launch_bounds__(256) k_all(const float* __restrict__ scores,
                                             float* __restrict__ out,
                                             int write_density) {
    __shared__ unsigned hist[HSIZE];
    __shared__ unsigned cand[MAXCAND];
    __shared__ unsigned s_cnthi, s_ncand, s_pivotkey, s_tot;
    __shared__ unsigned s_rel, s_base;

    const int row  = blockIdx.x;
    const int t    = threadIdx.x;
    const int lane = t & 31, warp = t >> 5;

    // ---------------- per-row top-k ----------------
    hist[t] = 0u;
    if (t < HSIZE - 256) hist[256 + t] = 0u;
    if (t == 0) { s_cnthi = 0u; s_ncand = 0u; }
    __syncthreads();                                   // barrier 1

    unsigned key[16];
    const float4* src  = (const float4*)(scores + (size_t)row * LK);
    float4*       zdst = (float4*)(out + (size_t)row * LK);
    #pragma unroll
    for (int i = 0; i < 4; i++) {
        float4 v = __ldcs(src + t + i * 256);
        key[4 * i + 0] = fkey(v.x); key[4 * i + 1] = fkey(v.y);
        key[4 * i + 2] = fkey(v.z); key[4 * i + 3] = fkey(v.w);
    }
    const float4 z = make_float4(0.f, 0.f, 0.f, 0.f);
    #pragma unroll
    for (int i = 0; i < 4; i++) __stcs(zdst + t + i * 256, z);

    // Count above-window; histogram in-window keys (~8% of row)
    int chi = 0;
    #pragma unroll
    for (int e = 0; e < 16; e++) {
        unsigned k = key[e];
        if (k > KHI) chi++;
        else if (k >= KLO) atomicAdd(&hist[(KHI - k) >> BSHIFT], 1u);
    }
    #pragma unroll
    for (int off = 16; off; off >>= 1)
        chi += __shfl_down_sync(0xffffffffu, chi, off);
    if (lane == 0) atomicAdd(&s_cnthi, (unsigned)chi);
    __syncthreads();                                   // barrier 2

    // Redundant per-warp cumulative-from-top scan (no shared write, no barrier)
    const unsigned cnthi = s_cnthi;
    unsigned part = 0;
    #pragma unroll
    for (int i = 0; i < BPL; i++) part += hist[lane * BPL + i];
    unsigned pfx = part;
    #pragma unroll
    for (int s = 1; s < 32; s <<= 1) {
        unsigned v = __shfl_up_sync(0xffffffffu, pfx, s);
        if (lane >= s) pfx += v;
    }
    unsigned excl  = pfx - part;
    unsigned total = __shfl_sync(0xffffffffu, pfx, 31);
    unsigned cbase = cnthi + excl;
    unsigned packed = 0;
    if (cbase < KSEL && cbase + part >= KSEL) {
        unsigned acc = cbase;
        #pragma unroll
        for (int i = 0; i < BPL; i++) {
            unsigned hv = hist[lane * BPL + i];
            if (acc + hv >= KSEL) { packed = ((unsigned)(lane * BPL + i) << 16) | (KSEL - acc); break; }
            acc += hv;
        }
    }
    #pragma unroll
    for (int off = 16; off; off >>= 1)
        packed |= __shfl_xor_sync(0xffffffffu, packed, off);
    bool need_fb = (cnthi >= KSEL) || (cnthi + total < KSEL);  // uniform
    const int bin = (int)(packed >> 16);
    const int rem = (int)(packed & 0xFFFFu);

    if (!need_fb) {
        // Gather pivot-bin candidates (expected ~1), exact rank-select
        #pragma unroll
        for (int e = 0; e < 16; e++) {
            unsigned k = key[e];
            if (k <= KHI && k >= KLO && (int)((KHI - k) >> BSHIFT) == bin) {
                unsigned p = atomicAdd(&s_ncand, 1u);
                if (p < MAXCAND) cand[p] = k;
            }
        }
        __syncthreads();                               // barrier 3
        unsigned nc = s_ncand;                         // uniform
        if (nc <= MAXCAND) {
            if (t < (int)nc) {
                unsigned me = cand[t];
                int gcnt = 0, eq = 0;
                for (unsigned j = 0; j < nc; j++) {
                    unsigned v = cand[j];
                    gcnt += (v > me);
                    eq   += (v == me);
                }
                if (gcnt < rem && gcnt + eq >= rem) s_pivotkey = me;
            }
        } else {
            need_fb = true;                            // uniform overflow
        }
        __syncthreads();                               // barrier 4
    }

    if (need_fb) {
        // Exact fallback: MSB-first binary search on keys
        unsigned piv = 0;
        for (int bit = 31; bit >= 0; --bit) {
            unsigned candv = piv | (1u << bit);
            int c = 0;
            #pragma unroll
            for (int e = 0; e < 16; e++) c += (key[e] >= candv);
            #pragma unroll
            for (int off = 16; off; off >>= 1)
                c += __shfl_down_sync(0xffffffffu, c, off);
            if (t == 0) s_tot = 0u;
            __syncthreads();
            if (lane == 0) atomicAdd(&s_tot, (unsigned)c);
            __syncthreads();
            if (s_tot >= KSEL) piv = candv;
            __syncthreads();
        }
        if (t == 0) s_pivotkey = piv;
        __syncthreads();
    }

    const unsigned pivot = s_pivotkey;

    // Membership: element 4t+1024i+m. OR-merge 4-bit nibbles across each
    // 8-lane octet with 3 xor-shuffles; octet leader writes the word.
    unsigned* mrow = g_masks + (size_t)row * WORDS;
    #pragma unroll
    for (int i = 0; i < 4; i++) {
        unsigned nib = 0;
        #pragma unroll
        for (int m = 0; m < 4; m++) nib |= (unsigned)(key[4 * i + m] >= pivot) << m;
        unsigned wv = nib << (4 * (lane & 7));
        wv |= __shfl_xor_sync(0xffffffffu, wv, 1);
        wv |= __shfl_xor_sync(0xffffffffu, wv, 2);
        wv |= __shfl_xor_sync(0xffffffffu, wv, 4);
        if ((lane & 7) == 0) mrow[32 * i + 4 * warp + (lane >> 3)] = wv;
    }

    // ---------------- last-CTA tail election ----------------
    __threadfence();                    // masks visible before ticket
    if (t == 0) {
        unsigned pos = atomicAdd(&g_ctr, 1u);
        s_rel  = pos & (NROWS - 1);     // position within this launch
        s_base = pos - (pos & (NROWS - 1));
    }
    __syncthreads();
    if (s_rel < NROWS - H) return;      // uniform: not a tail block
    const int h = (int)s_rel - (NROWS - H);   // this block owns head h
    const int g = h / GS;

    // Wait until all NROWS blocks of this launch have finished
    if (t == 0) {
        const unsigned tbase = s_base;
        volatile unsigned* vc = &g_ctr;
        while (*vc - tbase < NROWS) {}
    }
    __syncthreads();
    __threadfence();

    // ---- Phase 1: nsel for head h (8 rows per barrier pair; stops at n~3) ----
    __shared__ int s_found, s_cnt, s_nstop;
    __shared__ int s_part[8][8];
    __shared__ unsigned su[WORDS];
    if (t == 0) { s_found = 0; s_cnt = 0; }
    __syncthreads();
    const unsigned* mbase = g_masks + (size_t)h * LQ * WORDS;
    unsigned un = 0;
    for (int n0 = 0; n0 < LQ; n0 += 8) {
        int adds[8];
        #pragma unroll
        for (int j = 0; j < 8; j++) {
            unsigned m = (t < 128) ? mbase[(size_t)(LQ - 1 - (n0 + j)) * WORDS + t] : 0u;
            adds[j] = __popc(m & ~un);
            un |= m;
        }
        #pragma unroll
        for (int j = 0; j < 8; j++) {
            #pragma unroll
            for (int off = 16; off; off >>= 1)
                adds[j] += __shfl_down_sync(0xffffffffu, adds[j], off);
            if (lane == 0) s_part[warp][j] = adds[j];
        }
        __syncthreads();
        if (t == 0) {
            for (int j = 0; j < 8 && !s_found; j++) {
                int sum = 0;
                #pragma unroll
                for (int w = 0; w < 8; w++) sum += s_part[w][j];
                s_cnt += sum;
                if (s_cnt >= THRESH) s_found = n0 + j + 1;
            }
        }
        __syncthreads();
        if (s_found) break;             // uniform
    }
    if (t == 0) {
        g_nsel[h] = s_found ? s_found : NOT_CHOSEN;
        __threadfence();
        atomicAdd(&g_bar1, 1u);
    }
    // Global counter barrier 1 (32 co-resident tail blocks; monotonic)
    if (t == 0) {
        volatile unsigned* vb = &g_bar1;
        unsigned a;
        do { a = *vb; } while ((a & (H - 1)) != 0u || a == 0u ? ((a & (H - 1)) != 0u) : false);
        // spin until count within this launch reaches H: (a mod H)==0 after all H arrive
    }
    __syncthreads();
    __threadfence();

    // n_stop from all heads (warp 0 of each tail block)
    if (warp == 0) {
        int v  = g_nsel[lane];
        int ch = (v < NOT_CHOSEN) ? 1 : 0;
        int mx = ch ? v : 1;
        #pragma unroll
        for (int off = 16; off; off >>= 1) {
            ch = min(ch, __shfl_down_sync(0xffffffffu, ch, off));
            mx = max(mx, __shfl_down_sync(0xffffffffu, mx, off));
        }
        if (lane == 0) s_nstop = ch ? mx : LQ;
    }
    __syncthreads();

    // ---- Phase 2: union of last n_stop rows of head h ----
    const int ns = s_nstop;
    if (t < 128) {
        unsigned u = 0;
        for (int n = 1; n <= ns; n++)
            u |= mbase[(size_t)(LQ - n) * WORDS + t];
        g_hunion[h * WORDS + t] = u;
    }
    __threadfence();
    __syncthreads();
    if (t == 0) atomicAdd(&g_bar2, 1u);
    // Global counter barrier 2
    if (t == 0) {
        volatile unsigned* vb = &g_bar2;
        while ((*vb & (H - 1)) != 0u) {}
    }
    __syncthreads();
    __threadfence();

    // Group-OR for this head's group; write last-row values for head h
    if (t < 128) {
        su[t] = g_hunion[(g * GS + 0) * WORDS + t]
              | g_hunion[(g * GS + 1) * WORDS + t]
              | g_hunion[(g * GS + 2) * WORDS + t]
              | g_hunion[(g * GS + 3) * WORDS + t];
    }
    __syncthreads();

    const float MINV = -3.402823466e38f;  // finfo(float32).min
    float* orow = out + ((size_t)h * LQ + (LQ - 1)) * LK;
    #pragma unroll
    for (int i = 0; i < 4; i++) {
        int c4 = t + i * 256;              // float4 index; cols 4*c4..4*c4+3
        unsigned w = su[c4 >> 3];
        float4 v;
        v.x = ((w >> ((4 * c4 + 0) & 31)) & 1u) ? 0.0f : MINV;
        v.y = ((w >> ((4 * c4 + 1) & 31)) & 1u) ? 0.0f : MINV;
        v.z = ((w >> ((4 * c4 + 2) & 31)) & 1u) ? 0.0f : MINV;
        v.w = ((w >> ((4 * c4 + 3) & 31)) & 1u) ? 0.0f : MINV;
        ((float4*)orow)[c4] = v;
    }

    // Density: head-0 tail block computes all 8 group unions' popcounts
    if (write_density && h == 0) {
        __shared__ int ws[8];
        int c = 0;
        for (int p = t; p < NG * WORDS; p += 256) {
            int gg = p >> 7, w = p & 127;
            unsigned gu = g_hunion[(gg * GS + 0) * WORDS + w]
                        | g_hunion[(gg * GS + 1) * WORDS + w]
                        | g_hunion[(gg * GS + 2) * WORDS + w]
                        | g_hunion[(gg * GS + 3) * WORDS + w];
            c += __popc(gu);
        }
        #pragma unroll
        for (int off = 16; off; off >>= 1)
            c += __shfl_down_sync(0xffffffffu, c, off);
        if (lane == 0) ws[warp] = c;
        __syncthreads();
        if (t == 0) {
            int total2 = 0;
            #pragma unroll
            for (int w = 0; w < 8; w++) total2 += ws[w];
            out[(size_t)H * LQ * LK] = (float)(GS * total2) / (float)(H * LK);
        }
    }
}

// ---------------------------------------------------------------------------
extern "C" void kernel_launch(void* const* d_in, const int* in_sizes, int n_in,
                              void* d_out, int out_size) {
    const float* scores = (const float*)d_in[0];
    float* out = (float*)d_out;
    k_all<<<NROWS, 256>>>(scores, out, out_size > H * LQ * LK ? 1 : 0);
}

// round 11
// speedup vs baseline: 1.1120x; 1.1120x over previous
#include <cuda_runtime.h>
#include <cstdint>

// Problem constants (fixed by setup_inputs): B=1, H=32, Lq=512, Lk=4096, group_size=4
#define H       32
#define LQ      512
#define LK      4096
#define WORDS   128            // LK / 32
#define KSEL    819            // int(0.2 * 4096)
#define THRESH  1638           // min(2*819, int(0.75*4096))
#define GS      4
#define NG      8              // H / GS
#define NOT_CHOSEN (1 << 30)
#define MAXCAND 64

// Value window for the 819th-largest of 4096 i.i.d. N(0,1) samples.
// Pivot concentrates at 0.8416 +- 0.022; [0.70, 1.00] is ~7 sigma.
// All values in-window are positive => plain float compares are exact.
// Exact key-domain fallback handles anything outside the window.
#define WLO 0.70f
#define WHI 1.00f
#define WSCALE (256.0f / (WHI - WLO))

// Scratch (device globals; no allocation allowed)
__device__ unsigned g_masks[(size_t)H * LQ * WORDS];   // 8 MB of top-k bitsets
__device__ unsigned g_hunion[H * WORDS];
__device__ int      g_nsel[H];
__device__ int      g_gcnt[NG];
__device__ int      g_done[H];       // barrier-1 flags (reset by k_topk block 0)
__device__ int      g_done2[H];      // barrier-2 flags
__device__ int      g_done3[NG];     // density flags

// Order-preserving float -> uint32 map (fallback path only)
__device__ __forceinline__ unsigned fkey(float f) {
    unsigned u = __float_as_uint(f);
    return (u & 0x80000000u) ? ~u : (u | 0x80000000u);
}
__device__ __forceinline__ float unfkey(unsigned k) {
    unsigned u = (k & 0x80000000u) ? (k & 0x7FFFFFFFu) : ~k;
    return __uint_as_float(u);
}

// ---------------------------------------------------------------------------
// Kernel 1: per-row exact top-k mask, all-float hot path (no key conversion).
// Windowed 256-bin histogram + exact candidate refinement; exact key-domain
// binary-search fallback. Zeros this row of the output. 4 block barriers.
// grid = H*LQ blocks, 256 threads; each block owns one row of 4096 floats.
// ---------------------------------------------------------------------------
__global__ void __launch_bounds__(256) k_topk(const float* __restrict__ scores,
                                              float* __restrict__ out) {
    __shared__ unsigned hist[256];
    __shared__ float cand[MAXCAND];
    __shared__ unsigned s_cnthi, s_ncand, s_tot;
    __shared__ float s_pivot;

    const int row  = blockIdx.x;
    const int t    = threadIdx.x;
    const int lane = t & 31, warp = t >> 5;

    // Reset k_tail flags once per launch (kernel boundary orders this vs k_tail)
    if (row == 0) {
        if (t < H)  { g_done[t] = 0; g_done2[t] = 0; }
        if (t < NG) g_done3[t] = 0;
    }

    hist[t] = 0u;
    if (t == 0) { s_cnthi = 0u; s_ncand = 0u; }
    __syncthreads();                                   // barrier 1

    // Load 16 elements/thread (coalesced float4); zero the output row.
    float x[16];
    const float4* src  = (const float4*)(scores + (size_t)row * LK);
    float4*       zdst = (float4*)(out + (size_t)row * LK);
    #pragma unroll
    for (int i = 0; i < 4; i++) {
        float4 v = __ldcs(src + t + i * 256);
        x[4 * i + 0] = v.x; x[4 * i + 1] = v.y;
        x[4 * i + 2] = v.z; x[4 * i + 3] = v.w;
    }
    const float4 z = make_float4(0.f, 0.f, 0.f, 0.f);
    #pragma unroll
    for (int i = 0; i < 4; i++) __stcs(zdst + t + i * 256, z);

    // Count above-window; histogram in-window values (~8% of row)
    int chi = 0;
    #pragma unroll
    for (int e = 0; e < 16; e++) {
        float v = x[e];
        if (v > WHI) {
            chi++;
        } else if (v >= WLO) {
            int b = (int)((WHI - v) * WSCALE);
            if (b > 255) b = 255;
            atomicAdd(&hist[b], 1u);
        }
    }
    #pragma unroll
    for (int off = 16; off; off >>= 1)
        chi += __shfl_down_sync(0xffffffffu, chi, off);
    if (lane == 0) atomicAdd(&s_cnthi, (unsigned)chi);
    __syncthreads();                                   // barrier 2

    // Redundant per-warp cumulative-from-top scan (bin 0 = largest values);
    // result broadcast warp-locally, no shared write, no extra barrier.
    const unsigned cnthi = s_cnthi;
    unsigned part = 0;
    #pragma unroll
    for (int i = 0; i < 8; i++) part += hist[lane * 8 + i];
    unsigned pfx = part;
    #pragma unroll
    for (int s = 1; s < 32; s <<= 1) {
        unsigned v = __shfl_up_sync(0xffffffffu, pfx, s);
        if (lane >= s) pfx += v;
    }
    unsigned excl  = pfx - part;
    unsigned total = __shfl_sync(0xffffffffu, pfx, 31);
    unsigned cbase = cnthi + excl;
    unsigned packed = 0;
    if (cbase < KSEL && cbase + part >= KSEL) {
        unsigned acc = cbase;
        #pragma unroll
        for (int i = 0; i < 8; i++) {
            unsigned hv = hist[lane * 8 + i];
            if (acc + hv >= KSEL) { packed = ((unsigned)(lane * 8 + i) << 16) | (KSEL - acc); break; }
            acc += hv;
        }
    }
    #pragma unroll
    for (int off = 16; off; off >>= 1)
        packed |= __shfl_xor_sync(0xffffffffu, packed, off);
    bool need_fb = (cnthi >= KSEL) || (cnthi + total < KSEL);  // uniform
    const int bin = (int)(packed >> 16);
    const int rem = (int)(packed & 0xFFFFu);

    if (!need_fb) {
        // Gather pivot-bin candidates (expected ~1.3), exact rank-select
        #pragma unroll
        for (int e = 0; e < 16; e++) {
            float v = x[e];
            if (v <= WHI && v >= WLO) {
                int b = (int)((WHI - v) * WSCALE);
                if (b > 255) b = 255;
                if (b == bin) {
                    unsigned p = atomicAdd(&s_ncand, 1u);
                    if (p < MAXCAND) cand[p] = v;
                }
            }
        }
        __syncthreads();                               // barrier 3
        unsigned nc = s_ncand;                         // uniform after barrier
        if (nc <= MAXCAND) {
            if (t < (int)nc) {
                float me = cand[t];
                int gcnt = 0, eq = 0;
                for (unsigned j = 0; j < nc; j++) {
                    float v = cand[j];
                    gcnt += (v > me);
                    eq   += (v == me);
                }
                if (gcnt < rem && gcnt + eq >= rem) s_pivot = me;
            }
        } else {
            need_fb = true;                            // uniform overflow
        }
        __syncthreads();                               // barrier 4
    }

    if (need_fb) {
        // Exact fallback: MSB-first binary search on order-preserving keys
        unsigned piv = 0;
        for (int bit = 31; bit >= 0; --bit) {
            unsigned candv = piv | (1u << bit);
            int c = 0;
            #pragma unroll
            for (int e = 0; e < 16; e++) c += (fkey(x[e]) >= candv);
            #pragma unroll
            for (int off = 16; off; off >>= 1)
                c += __shfl_down_sync(0xffffffffu, c, off);
            if (t == 0) s_tot = 0u;
            __syncthreads();
            if (lane == 0) atomicAdd(&s_tot, (unsigned)c);
            __syncthreads();
            if (s_tot >= KSEL) piv = candv;
            __syncthreads();
        }
        if (t == 0) s_pivot = unfkey(piv);
        __syncthreads();
    }

    const float pivot = s_pivot;

    // Membership: element 4t+1024i+m. OR-merge 4-bit nibbles across each
    // 8-lane octet with 3 xor-shuffles; octet leader writes the word.
    unsigned* mrow = g_masks + (size_t)row * WORDS;
    #pragma unroll
    for (int i = 0; i < 4; i++) {
        unsigned nib = 0;
        #pragma unroll
        for (int m = 0; m < 4; m++) nib |= (unsigned)(x[4 * i + m] >= pivot) << m;
        unsigned wv = nib << (4 * (lane & 7));
        wv |= __shfl_xor_sync(0xffffffffu, wv, 1);
        wv |= __shfl_xor_sync(0xffffffffu, wv, 2);
        wv |= __shfl_xor_sync(0xffffffffu, wv, 4);
        if ((lane & 7) == 0) mrow[32 * i + 4 * warp + (lane >> 3)] = wv;
    }
}

// ---------------------------------------------------------------------------
// Kernel 2 (fused tail): one block per head (32 blocks, always co-resident).
// Phase 1: per-head back-to-front scan (parallel across heads). Spin barrier.
// n_stop. Phase 2: per-head union. Spin barrier. Group-OR + last-row write
// (spread over 32 blocks) + density. All __syncthreads() unconditional.
// (Round-7 structure verbatim — measured 11.5 us.)
// ---------------------------------------------------------------------------
__global__ void __launch_bounds__(256) k_tail(float* __restrict__ out, int write_density) {
    const int h = blockIdx.x;          // 0..31
    const int g = h / GS;
    const int t = threadIdx.x;
    const int lane = t & 31, warp = t >> 5;
    __shared__ int s_found, s_cnt, s_nstop;
    __shared__ int ws[8];
    __shared__ unsigned su[WORDS];

    // ---- Phase 1: nsel for head h ----
    if (t == 0) { s_found = 0; s_cnt = 0; }
    __syncthreads();
    const unsigned* base = g_masks + (size_t)h * LQ * WORDS;
    unsigned un = 0;
    for (int n = 1; n <= LQ; n++) {
        unsigned m = (t < 128) ? base[(size_t)(LQ - n) * WORDS + t] : 0u;
        int add = __popc(m & ~un);
        un |= m;
        #pragma unroll
        for (int off = 16; off; off >>= 1)
            add += __shfl_down_sync(0xffffffffu, add, off);
        if (lane == 0) ws[warp] = add;
        __syncthreads();
        if (t == 0) {
            int sum = 0;
            #pragma unroll
            for (int w = 0; w < 8; w++) sum += ws[w];
            s_cnt += sum;
            if (!s_found && s_cnt >= THRESH) s_found = n;
        }
        __syncthreads();
        if (s_found) break;            // uniform: decided from shared state
    }
    if (t == 0) {
        g_nsel[h] = s_found ? s_found : NOT_CHOSEN;
        __threadfence();
        atomicExch(&g_done[h], 1);
    }

    // ---- Global barrier 1 (32 co-resident blocks) ----
    if (t < H) {
        volatile int* vd = g_done;
        while (vd[t] == 0) {}
    }
    __syncthreads();
    __threadfence();

    // n_stop from all heads (warp 0)
    if (warp == 0) {
        int v  = g_nsel[lane];
        int ch = (v < NOT_CHOSEN) ? 1 : 0;
        int mx = ch ? v : 1;
        #pragma unroll
        for (int off = 16; off; off >>= 1) {
            ch = min(ch, __shfl_down_sync(0xffffffffu, ch, off));
            mx = max(mx, __shfl_down_sync(0xffffffffu, mx, off));
        }
        if (lane == 0) s_nstop = ch ? mx : LQ;
    }
    __syncthreads();

    // ---- Phase 2: union of last n_stop rows of head h ----
    const int ns = s_nstop;
    if (t < 128) {
        unsigned u = 0;
        for (int n = 1; n <= ns; n++)
            u |= base[(size_t)(LQ - n) * WORDS + t];
        g_hunion[h * WORDS + t] = u;
    }
    __threadfence();
    __syncthreads();
    if (t == 0) atomicExch(&g_done2[h], 1);

    // ---- Global barrier 2 ----
    if (t < H) {
        volatile int* vd = g_done2;
        while (vd[t] == 0) {}
    }
    __syncthreads();
    __threadfence();

    // Group-OR for this head's group
    if (t < 128) {
        unsigned gu = g_hunion[(g * GS + 0) * WORDS + t]
                    | g_hunion[(g * GS + 1) * WORDS + t]
                    | g_hunion[(g * GS + 2) * WORDS + t]
                    | g_hunion[(g * GS + 3) * WORDS + t];
        su[t] = gu;
        int c = __popc(gu);
        #pragma unroll
        for (int off = 16; off; off >>= 1)
            c += __shfl_down_sync(0xffffffffu, c, off);
        if (lane == 0) ws[warp] = c;
    }
    __syncthreads();

    // Last-row values for head h (float4 stores, 16 KB per block)
    const float MINV = -3.402823466e38f;  // finfo(float32).min
    float* orow = out + ((size_t)h * LQ + (LQ - 1)) * LK;
    #pragma unroll
    for (int i = 0; i < 4; i++) {
        int c4 = t + i * 256;              // float4 index; cols 4*c4..4*c4+3
        unsigned w = su[c4 >> 3];
        float4 v;
        v.x = ((w >> ((4 * c4 + 0) & 31)) & 1u) ? 0.0f : MINV;
        v.y = ((w >> ((4 * c4 + 1) & 31)) & 1u) ? 0.0f : MINV;
        v.z = ((w >> ((4 * c4 + 2) & 31)) & 1u) ? 0.0f : MINV;
        v.w = ((w >> ((4 * c4 + 3) & 31)) & 1u) ? 0.0f : MINV;
        ((float4*)orow)[c4] = v;
    }

    // Density: group-leader blocks publish; block 0 aggregates
    if (write_density) {
        if ((h & (GS - 1)) == 0 && t == 0) {
            g_gcnt[g] = GS * (ws[0] + ws[1] + ws[2] + ws[3]);
            __threadfence();
            atomicExch(&g_done3[g], 1);
        }
        if (h == 0) {
            if (t < NG) {
                volatile int* vd = g_done3;
                while (vd[t] == 0) {}
            }
            __syncthreads();
            __threadfence();
            if (t == 0) {
                int total = 0;
                #pragma unroll
                for (int i = 0; i < NG; i++) total += g_gcnt[i];
                out[(size_t)H * LQ * LK] = (float)total / (float)(H * LK);
            }
        }
    }
}

// ---------------------------------------------------------------------------
extern "C" void kernel_launch(void* const* d_in, const int* in_sizes, int n_in,
                              void* d_out, int out_size) {
    const float* scores = (const float*)d_in[0];
    float* out = (float*)d_out;

    k_topk<<<H * LQ, 256>>>(scores, out);   // also zeros output rows + resets flags
    k_tail<<<H, 256>>>(out, out_size > H * LQ * LK ? 1 : 0);
}